// round 12
// baseline (speedup 1.0000x reference)
#include <cuda_runtime.h>
#include <cuda_fp16.h>
#include <math.h>
#include <stdint.h>

// ==========================================================================
// DepthAwareTokenAggregator — single-pass fp16 HMMA (sm_103-safe)
// R10: R9 (k=64 chunks, double-buffered B) with the buffer-reuse race fixed:
//      refill of buffer (c&1) is issued only after a tail barrier proving all
//      warps finished reading chunk c from that buffer.
// ==========================================================================

#define SA_E   264u                // A row stride in fp16 elems (528B, odd granules)
#define SA_B   528u
#define STRB   144u                // B row stride bytes (9 granules, odd)
#define OFF_B   33792u             // 64 * 528
#define BUFSZ   36864u             // 256 rows * 144B (one k=64 chunk)
#define OFF_SCR 107520u            // OFF_B + 2*BUFSZ
#define SMEM_TOTAL 110592u         // 108KB -> 2 CTAs/SM

__device__ __align__(16) __half g_Bh[256 * 256];

// W1[k][n] -> Bh[n][k] fp16 for k < 256 (k=256 slab handled in fp32 epilogue)
__global__ void prep_B(const float* __restrict__ W1) {
    int n = blockIdx.x, k = threadIdx.x;
    g_Bh[n * 256 + k] = __float2half_rn(W1[(size_t)k * 256 + n]);
}

__device__ __forceinline__ uint32_t smem_u32(const void* p) {
    uint32_t a;
    asm("{ .reg .u64 t; cvta.to.shared.u64 t, %1; cvt.u32.u64 %0, t; }" : "=r"(a) : "l"(p));
    return a;
}
__device__ __forceinline__ void mma16816(float* d, const uint32_t* a, const uint32_t* b) {
    asm volatile("mma.sync.aligned.m16n8k16.row.col.f32.f16.f16.f32 "
                 "{%0,%1,%2,%3}, {%4,%5,%6,%7}, {%8,%9}, {%0,%1,%2,%3};"
                 : "+f"(d[0]), "+f"(d[1]), "+f"(d[2]), "+f"(d[3])
                 : "r"(a[0]), "r"(a[1]), "r"(a[2]), "r"(a[3]), "r"(b[0]), "r"(b[1]));
}
__device__ __forceinline__ void ldmat4(uint32_t& r0, uint32_t& r1, uint32_t& r2, uint32_t& r3,
                                       uint32_t addr) {
    asm volatile("ldmatrix.sync.aligned.m8n8.x4.shared.b16 {%0,%1,%2,%3}, [%4];"
                 : "=r"(r0), "=r"(r1), "=r"(r2), "=r"(r3) : "r"(addr));
}
// GELU with Abramowitz-Stegun 7.1.26 erf (|eps| <= 1.5e-7)
__device__ __forceinline__ float gelu_f(float h) {
    float ax = fabsf(h) * 0.70710678118654752f;
    float t  = __fdividef(1.0f, fmaf(0.3275911f, ax, 1.0f));
    float p  = fmaf(t, 1.061405429f, -1.453152027f);
    p = fmaf(t, p, 1.421413741f);
    p = fmaf(t, p, -0.284496736f);
    p = fmaf(t, p, 0.254829592f);
    p = p * t;
    float e  = __expf(-ax * ax);
    float er = copysignf(fmaf(-p, e, 1.0f), h);
    return 0.5f * h * (1.0f + er);
}
// convert 8 floats (two float4) to 4 packed fp16 pairs
__device__ __forceinline__ uint4 cvt8(float4 v0, float4 v1) {
    uint4 r;
    r.x = (uint32_t)__half_as_ushort(__float2half_rn(v0.x)) |
          ((uint32_t)__half_as_ushort(__float2half_rn(v0.y)) << 16);
    r.y = (uint32_t)__half_as_ushort(__float2half_rn(v0.z)) |
          ((uint32_t)__half_as_ushort(__float2half_rn(v0.w)) << 16);
    r.z = (uint32_t)__half_as_ushort(__float2half_rn(v1.x)) |
          ((uint32_t)__half_as_ushort(__float2half_rn(v1.y)) << 16);
    r.w = (uint32_t)__half_as_ushort(__float2half_rn(v1.z)) |
          ((uint32_t)__half_as_ushort(__float2half_rn(v1.w)) << 16);
    return r;
}

// Load one k=64 B chunk into buffer buf via cp.async (256 threads, 8 ops each).
__device__ __forceinline__ void issue_chunk(uint32_t sbase, int c, int buf) {
    const uint32_t dstb = sbase + OFF_B + (uint32_t)buf * BUFSZ;
    const int tid = threadIdx.x;
    #pragma unroll
    for (int i = 0; i < 8; ++i) {
        int op = i * 256 + tid;                  // 0..2047
        int n = op >> 3, q = op & 7;
        const void* src = g_Bh + (size_t)n * 256 + c * 64 + q * 8;
        uint32_t dst = dstb + (uint32_t)n * STRB + (uint32_t)q * 16u;
        asm volatile("cp.async.cg.shared.global [%0], [%1], 16;" :: "r"(dst), "l"(src));
    }
    asm volatile("cp.async.commit_group;" ::: "memory");
}

extern __shared__ char smem[];

__global__ __launch_bounds__(256, 2)
void dat_hmma_kernel(const float* __restrict__ sampled,   // [4096,64,256]
                     const float* __restrict__ valid,     // [4096,64]
                     const float* __restrict__ y_norm,    // [64]
                     const float* __restrict__ W1,        // [257,256]
                     const float* __restrict__ b1,        // [256]
                     const float* __restrict__ W2,        // [256]
                     const float* __restrict__ b2,        // [1]
                     float* __restrict__ out)             // [4096,256]
{
    const uint32_t sbase = smem_u32(smem);
    const int tid = threadIdx.x, wid = tid >> 5, lane = tid & 31;
    const int wm = wid & 1;                      // M-warp: rows wm*32..wm*32+31
    const int wn = wid >> 1;                     // N-warp: cols wn*64..wn*64+63
    const int bx = blockIdx.x;                   // token id

    float* spart = reinterpret_cast<float*>(smem + OFF_SCR);        // [4][64]
    float* slog  = spart + 256;                                      // [64]
    float* sval  = slog + 64;                                        // [64]
    float* swts  = sval + 64;                                        // [64]
    float* sW256 = swts + 64;                                        // [256]
    float* sY    = sW256 + 256;                                      // [64]

    // kick off both B buffers (chunks 0, 1)
    issue_chunk(sbase, 0, 0);
    issue_chunk(sbase, 1, 1);

    const float* src = sampled + (size_t)bx * 64 * 256;
    // per-thread A mapping: row = tid>>2 (0..63), 16 k at (tid&3)*16 within chunk
    const int arow = tid >> 2;
    const int aq   = tid & 3;
    const float4* asrc = reinterpret_cast<const float4*>(src + (size_t)arow * 256) + 4 * aq;
    const uint32_t abyte = (uint32_t)arow * SA_B + (uint32_t)aq * 32u;  // 16 fp16 = 32B

    // epilogue constants (scratch untouched by mainloop)
    sW256[tid] = W1[256 * 256 + tid];
    if (tid < 64) { sY[tid] = y_norm[tid]; sval[tid] = valid[(size_t)bx * 64 + tid]; }

    // ---- prologue: convert A chunk 0 (k 0..63) ----
    {
        float4 v0 = asrc[0], v1 = asrc[1], v2 = asrc[2], v3 = asrc[3];
        *reinterpret_cast<uint4*>(smem + abyte)       = cvt8(v0, v1);
        *reinterpret_cast<uint4*>(smem + abyte + 16u) = cvt8(v2, v3);
    }

    // ---- main loop: 4 chunks of k=64, double-buffered B ----
    float acc[2][8][4];
    #pragma unroll
    for (int a = 0; a < 2; ++a)
        #pragma unroll
        for (int b = 0; b < 8; ++b)
            #pragma unroll
            for (int d = 0; d < 4; ++d) acc[a][b][d] = 0.0f;

    const uint32_t a_lane = (uint32_t)(lane & 15) * SA_B + (uint32_t)(lane >> 4) * 16u;
    const uint32_t g = (uint32_t)(lane >> 3);
    const uint32_t nrow = (uint32_t)(wn * 64) + ((g >> 1) * 8u) + (uint32_t)(lane & 7);

    #pragma unroll 1
    for (int c = 0; c < 4; ++c) {
        if (c < 3) asm volatile("cp.async.wait_group 1;" ::: "memory");
        else       asm volatile("cp.async.wait_group 0;" ::: "memory");
        __syncthreads();   // chunk c visible; A chunk c stored (prev iter)

        const bool do_conv = (c < 3);
        const uint32_t bbase = sbase + OFF_B + (uint32_t)(c & 1) * BUFSZ;
        const uint32_t adst = abyte + (uint32_t)(c + 1) * 128u;

        float4 pv0, pv1;
        if (do_conv) { pv0 = asrc[(c + 1) * 16]; pv1 = asrc[(c + 1) * 16 + 1]; }

        #pragma unroll
        for (int half = 0; half < 2; ++half) {
            #pragma unroll
            for (int kss = 0; kss < 2; ++kss) {
                const int ks = half * 2 + kss;
                uint32_t ah[2][4];
                #pragma unroll
                for (int mt = 0; mt < 2; ++mt) {
                    uint32_t ab = (uint32_t)(wm * 32 + mt * 16) * SA_B
                                + (uint32_t)(c * 64 + ks * 16) * 2u + a_lane;
                    ldmat4(ah[mt][0], ah[mt][1], ah[mt][2], ah[mt][3], sbase + ab);
                }
                const uint32_t kbyt = ((uint32_t)(ks * 16) + (g & 1) * 8u) * 2u;
                const uint32_t baddr = nrow * STRB + kbyt;

                uint32_t bb[8][2];
                #pragma unroll
                for (int g2 = 0; g2 < 4; ++g2)
                    ldmat4(bb[2 * g2][0], bb[2 * g2][1], bb[2 * g2 + 1][0], bb[2 * g2 + 1][1],
                           bbase + baddr + (uint32_t)g2 * 16u * STRB);
                #pragma unroll
                for (int mt = 0; mt < 2; ++mt)
                    #pragma unroll
                    for (int nt = 0; nt < 8; ++nt) mma16816(acc[mt][nt], ah[mt], bb[nt]);
            }
            // interleave A conversion between the two ks-halves (reg-pressure safe)
            if (do_conv) {
                if (half == 0) {
                    *reinterpret_cast<uint4*>(smem + adst) = cvt8(pv0, pv1);
                    pv0 = asrc[(c + 1) * 16 + 2]; pv1 = asrc[(c + 1) * 16 + 3];
                } else {
                    *reinterpret_cast<uint4*>(smem + adst + 16u) = cvt8(pv0, pv1);
                }
            }
        }

        // refill the buffer we just finished reading — only after ALL warps
        // are done with it (tail barrier), avoiding the R9 write/read race.
        if (c + 2 < 4) {
            __syncthreads();
            issue_chunk(sbase, c + 2, c & 1);
        }
    }

    // ---- epilogue: fp32 rank-1 y_norm term, bias + GELU + W2 dot ----
    const int r0 = wm * 32 + (lane >> 2);
    float s0[2] = {0.f, 0.f}, s1[2] = {0.f, 0.f};
    #pragma unroll
    for (int mt = 0; mt < 2; ++mt) {
        const float yv0 = sY[r0 + mt * 16];
        const float yv1 = sY[r0 + mt * 16 + 8];
        #pragma unroll
        for (int nt = 0; nt < 8; ++nt) {
            int col = wn * 64 + nt * 8 + 2 * (lane & 3);
            float2 wv  = *reinterpret_cast<const float2*>(&sW256[col]);
            float2 bbv = *reinterpret_cast<const float2*>(&b1[col]);
            float2 wwv = *reinterpret_cast<const float2*>(&W2[col]);
            float h0 = fmaf(yv0, wv.x, acc[mt][nt][0]) + bbv.x;
            float h1 = fmaf(yv0, wv.y, acc[mt][nt][1]) + bbv.y;
            float h2 = fmaf(yv1, wv.x, acc[mt][nt][2]) + bbv.x;
            float h3 = fmaf(yv1, wv.y, acc[mt][nt][3]) + bbv.y;
            s0[mt] += gelu_f(h0) * wwv.x;
            s0[mt] += gelu_f(h1) * wwv.y;
            s1[mt] += gelu_f(h2) * wwv.x;
            s1[mt] += gelu_f(h3) * wwv.y;
        }
    }
    #pragma unroll
    for (int mt = 0; mt < 2; ++mt) {
        s0[mt] += __shfl_xor_sync(0xffffffffu, s0[mt], 1);
        s0[mt] += __shfl_xor_sync(0xffffffffu, s0[mt], 2);
        s1[mt] += __shfl_xor_sync(0xffffffffu, s1[mt], 1);
        s1[mt] += __shfl_xor_sync(0xffffffffu, s1[mt], 2);
    }

    if ((lane & 3) == 0) {
        #pragma unroll
        for (int mt = 0; mt < 2; ++mt) {
            spart[wn * 64 + r0 + mt * 16]     = s0[mt];
            spart[wn * 64 + r0 + mt * 16 + 8] = s1[mt];
        }
    }
    __syncthreads();

    if (tid < 64) {
        float lg = spart[tid] + spart[64 + tid] + spart[128 + tid] + spart[192 + tid] + b2[0];
        if (sval[tid] < 0.5f) lg = -10000.0f;
        slog[tid] = lg;
    }
    __syncthreads();

    if (wid == 0) {                               // softmax over 64 y for this token
        float l0 = slog[lane], l1 = slog[32 + lane];
        float v0 = sval[lane], v1 = sval[32 + lane];
        float mx = fmaxf(l0, l1);
        #pragma unroll
        for (int s = 16; s > 0; s >>= 1) mx = fmaxf(mx, __shfl_xor_sync(0xffffffffu, mx, s));
        float e0 = expf(l0 - mx), e1 = expf(l1 - mx);
        float z = e0 + e1;
        #pragma unroll
        for (int s = 16; s > 0; s >>= 1) z += __shfl_xor_sync(0xffffffffu, z, s);
        float w0 = (e0 / z) * v0, w1 = (e1 / z) * v1;
        float s2 = w0 + w1;
        #pragma unroll
        for (int s = 16; s > 0; s >>= 1) s2 += __shfl_xor_sync(0xffffffffu, s2, s);
        float denom = fmaxf(s2, 1e-6f);
        swts[lane]      = w0 / denom;
        swts[32 + lane] = w1 / denom;
    }
    __syncthreads();

    // ---- out[bx][c] = sum_y w[y] * A_hi[y][c] from resident tile ----
    {
        const __half* Hi = reinterpret_cast<const __half*>(smem);
        float a = 0.f;
        #pragma unroll 8
        for (int y = 0; y < 64; ++y)
            a = fmaf(swts[y], __half2float(Hi[(uint32_t)y * SA_E + (uint32_t)tid]), a);
        out[(size_t)bx * 256 + tid] = a;
    }
}

extern "C" void kernel_launch(void* const* d_in, const int* in_sizes, int n_in,
                              void* d_out, int out_size) {
    (void)in_sizes; (void)n_in; (void)out_size;
    const float* sampled = (const float*)d_in[0];
    const float* valid   = (const float*)d_in[1];
    const float* y_norm  = (const float*)d_in[2];
    const float* W1      = (const float*)d_in[3];
    const float* b1      = (const float*)d_in[4];
    const float* W2      = (const float*)d_in[5];
    const float* b2      = (const float*)d_in[6];

    prep_B<<<256, 256>>>(W1);

    cudaFuncSetAttribute(dat_hmma_kernel, cudaFuncAttributeMaxDynamicSharedMemorySize, SMEM_TOTAL);
    dat_hmma_kernel<<<4096, 256, SMEM_TOTAL>>>(sampled, valid, y_norm, W1, b1, W2, b2, (float*)d_out);
}

// round 15
// speedup vs baseline: 1.5878x; 1.5878x over previous
#include <cuda_runtime.h>
#include <cuda_fp16.h>
#include <math.h>
#include <stdint.h>

// ==========================================================================
// DepthAwareTokenAggregator — single-pass fp16 HMMA (sm_103-safe)
// R12: R7 warp shape (8 warps m32xn64, 256 thr, 2 CTAs/SM), but ZERO block
//      barriers in the mainloop: A converted fully upfront; B streamed per
//      warp-pair (producer warp + named barrier, private triple buffer).
// ==========================================================================

#define SA_E   264u                // A row stride in fp16 elems (528B, odd granules)
#define SA_B   528u
#define STRB   80u                 // B row stride bytes (5 granules, odd -> conflict-free)
#define OFF_B   33792u             // A region: 64 * 528
#define PAIRSZ  15360u             // per-pair B region: 3 bufs * 5120
#define BUFSZ   5120u              // 64 rows * 80B (one k=32 chunk for one pair)
#define OFF_SCR 95232u             // OFF_B + 4*PAIRSZ
#define SMEM_TOTAL 98304u          // 96KB -> 2 CTAs/SM

__device__ __align__(16) __half g_Bh[256 * 256];

// W1[k][n] -> Bh[n][k] fp16 for k < 256 (k=256 slab handled in fp32 epilogue)
__global__ void prep_B(const float* __restrict__ W1) {
    int n = blockIdx.x, k = threadIdx.x;
    g_Bh[n * 256 + k] = __float2half_rn(W1[(size_t)k * 256 + n]);
}

__device__ __forceinline__ uint32_t smem_u32(const void* p) {
    uint32_t a;
    asm("{ .reg .u64 t; cvta.to.shared.u64 t, %1; cvt.u32.u64 %0, t; }" : "=r"(a) : "l"(p));
    return a;
}
__device__ __forceinline__ void mma16816(float* d, const uint32_t* a, const uint32_t* b) {
    asm volatile("mma.sync.aligned.m16n8k16.row.col.f32.f16.f16.f32 "
                 "{%0,%1,%2,%3}, {%4,%5,%6,%7}, {%8,%9}, {%0,%1,%2,%3};"
                 : "+f"(d[0]), "+f"(d[1]), "+f"(d[2]), "+f"(d[3])
                 : "r"(a[0]), "r"(a[1]), "r"(a[2]), "r"(a[3]), "r"(b[0]), "r"(b[1]));
}
__device__ __forceinline__ void ldmat4(uint32_t& r0, uint32_t& r1, uint32_t& r2, uint32_t& r3,
                                       uint32_t addr) {
    asm volatile("ldmatrix.sync.aligned.m8n8.x4.shared.b16 {%0,%1,%2,%3}, [%4];"
                 : "=r"(r0), "=r"(r1), "=r"(r2), "=r"(r3) : "r"(addr));
}
// GELU with Abramowitz-Stegun 7.1.26 erf (|eps| <= 1.5e-7)
__device__ __forceinline__ float gelu_f(float h) {
    float ax = fabsf(h) * 0.70710678118654752f;
    float t  = __fdividef(1.0f, fmaf(0.3275911f, ax, 1.0f));
    float p  = fmaf(t, 1.061405429f, -1.453152027f);
    p = fmaf(t, p, 1.421413741f);
    p = fmaf(t, p, -0.284496736f);
    p = fmaf(t, p, 0.254829592f);
    p = p * t;
    float e  = __expf(-ax * ax);
    float er = copysignf(fmaf(-p, e, 1.0f), h);
    return 0.5f * h * (1.0f + er);
}
// convert 8 floats (two float4) to 4 packed fp16 pairs
__device__ __forceinline__ uint4 cvt8(float4 v0, float4 v1) {
    uint4 r;
    r.x = (uint32_t)__half_as_ushort(__float2half_rn(v0.x)) |
          ((uint32_t)__half_as_ushort(__float2half_rn(v0.y)) << 16);
    r.y = (uint32_t)__half_as_ushort(__float2half_rn(v0.z)) |
          ((uint32_t)__half_as_ushort(__float2half_rn(v0.w)) << 16);
    r.z = (uint32_t)__half_as_ushort(__float2half_rn(v1.x)) |
          ((uint32_t)__half_as_ushort(__float2half_rn(v1.y)) << 16);
    r.w = (uint32_t)__half_as_ushort(__float2half_rn(v1.z)) |
          ((uint32_t)__half_as_ushort(__float2half_rn(v1.w)) << 16);
    return r;
}

// Producer warp (32 threads): load its pair's k=32 B chunk into buffer buf.
__device__ __forceinline__ void issue_pair_chunk(uint32_t sbase, int wn, int lane,
                                                 int c, int buf) {
    const uint32_t dstb = sbase + OFF_B + (uint32_t)wn * PAIRSZ + (uint32_t)buf * BUFSZ;
    #pragma unroll
    for (int i = 0; i < 8; ++i) {
        int o = lane + 32 * i;                   // 0..255
        int nl = o >> 2, q = o & 3;
        const void* src = g_Bh + (size_t)(wn * 64 + nl) * 256 + c * 32 + q * 8;
        uint32_t dst = dstb + (uint32_t)nl * STRB + (uint32_t)q * 16u;
        asm volatile("cp.async.cg.shared.global [%0], [%1], 16;" :: "r"(dst), "l"(src));
    }
    asm volatile("cp.async.commit_group;" ::: "memory");
}

extern __shared__ char smem[];

__global__ __launch_bounds__(256, 2)
void dat_hmma_kernel(const float* __restrict__ sampled,   // [4096,64,256]
                     const float* __restrict__ valid,     // [4096,64]
                     const float* __restrict__ y_norm,    // [64]
                     const float* __restrict__ W1,        // [257,256]
                     const float* __restrict__ b1,        // [256]
                     const float* __restrict__ W2,        // [256]
                     const float* __restrict__ b2,        // [1]
                     float* __restrict__ out)             // [4096,256]
{
    const uint32_t sbase = smem_u32(smem);
    const int tid = threadIdx.x, wid = tid >> 5, lane = tid & 31;
    const int wm = wid & 1;                      // M-warp: rows wm*32..wm*32+31
    const int wn = wid >> 1;                     // N-warp pair: cols wn*64..wn*64+63
    const int bx = blockIdx.x;                   // token id

    float* spart = reinterpret_cast<float*>(smem + OFF_SCR);        // [4][64]
    float* slog  = spart + 256;                                      // [64]
    float* sval  = slog + 64;                                        // [64]
    float* swts  = sval + 64;                                        // [64]
    float* sW256 = swts + 64;                                        // [256]
    float* sY    = sW256 + 256;                                      // [64]

    // producers preload chunks 0 and 1 into bufs 0,1 of their pair region
    if (wm == 0) {
        issue_pair_chunk(sbase, wn, lane, 0, 0);
        issue_pair_chunk(sbase, wn, lane, 1, 1);
    }

    // ---- prologue: convert ALL of A upfront (fp32 gmem -> fp16 smem) ----
    const float* src = sampled + (size_t)bx * 64 * 256;
    {
        const int arow = tid >> 2;               // 0..63
        const int kb   = (tid & 3) * 64;         // 64 contiguous k per thread
        const float4* ap = reinterpret_cast<const float4*>(src + (size_t)arow * 256 + kb);
        const uint32_t abyte = (uint32_t)arow * SA_B + (uint32_t)kb * 2u;
        #pragma unroll
        for (int w = 0; w < 4; ++w) {            // 4 waves of 16 floats
            float4 v0 = ap[4 * w], v1 = ap[4 * w + 1];
            float4 v2 = ap[4 * w + 2], v3 = ap[4 * w + 3];
            *reinterpret_cast<uint4*>(smem + abyte + (uint32_t)w * 32u)       = cvt8(v0, v1);
            *reinterpret_cast<uint4*>(smem + abyte + (uint32_t)w * 32u + 16u) = cvt8(v2, v3);
        }
    }
    // epilogue constants
    sW256[tid] = W1[256 * 256 + tid];
    if (tid < 64) { sY[tid] = y_norm[tid]; sval[tid] = valid[(size_t)bx * 64 + tid]; }
    __syncthreads();                             // the ONLY pre-epilogue block barrier

    // ---- main loop: 8 chunks, per-pair triple-buffered B, named-bar sync ----
    float acc[2][8][4];
    #pragma unroll
    for (int a = 0; a < 2; ++a)
        #pragma unroll
        for (int b = 0; b < 8; ++b)
            #pragma unroll
            for (int d = 0; d < 4; ++d) acc[a][b][d] = 0.0f;

    const uint32_t a_lane = (uint32_t)(lane & 15) * SA_B + (uint32_t)(lane >> 4) * 16u;
    const uint32_t g = (uint32_t)(lane >> 3);
    const uint32_t rloc = ((g >> 1) * 8u) + (uint32_t)(lane & 7);    // pair-local B row
    const uint32_t pairb = sbase + OFF_B + (uint32_t)wn * PAIRSZ;
    const int barid = 1 + wn;

    #pragma unroll 1
    for (int c = 0; c < 8; ++c) {
        if (wm == 0) {                           // producer: chunk c landed?
            if (c < 7) asm volatile("cp.async.wait_group 1;" ::: "memory");
            else       asm volatile("cp.async.wait_group 0;" ::: "memory");
        }
        asm volatile("bar.sync %0, 64;" :: "r"(barid) : "memory");
        // refill: buf (c+2)%3 was read at iter c-1; partner passed this bar => safe
        if (wm == 0 && c + 2 < 8)
            issue_pair_chunk(sbase, wn, lane, c + 2, (c + 2) % 3);

        const uint32_t bbase = pairb + (uint32_t)(c % 3) * BUFSZ;

        #pragma unroll
        for (int ks = 0; ks < 2; ++ks) {
            uint32_t ah[2][4];
            #pragma unroll
            for (int mt = 0; mt < 2; ++mt) {
                uint32_t ab = (uint32_t)(wm * 32 + mt * 16) * SA_B
                            + (uint32_t)(c * 32 + ks * 16) * 2u + a_lane;
                ldmat4(ah[mt][0], ah[mt][1], ah[mt][2], ah[mt][3], sbase + ab);
            }
            const uint32_t kbyt = ((uint32_t)(ks * 16) + (g & 1) * 8u) * 2u;
            const uint32_t baddr = bbase + rloc * STRB + kbyt;

            uint32_t bb[8][2];
            #pragma unroll
            for (int g2 = 0; g2 < 4; ++g2)
                ldmat4(bb[2 * g2][0], bb[2 * g2][1], bb[2 * g2 + 1][0], bb[2 * g2 + 1][1],
                       baddr + (uint32_t)g2 * 16u * STRB);
            #pragma unroll
            for (int mt = 0; mt < 2; ++mt)
                #pragma unroll
                for (int nt = 0; nt < 8; ++nt) mma16816(acc[mt][nt], ah[mt], bb[nt]);
        }
    }

    // ---- epilogue: fp32 rank-1 y_norm term, bias + GELU + W2 dot ----
    const int r0 = wm * 32 + (lane >> 2);
    float s0[2] = {0.f, 0.f}, s1[2] = {0.f, 0.f};
    #pragma unroll
    for (int mt = 0; mt < 2; ++mt) {
        const float yv0 = sY[r0 + mt * 16];
        const float yv1 = sY[r0 + mt * 16 + 8];
        #pragma unroll
        for (int nt = 0; nt < 8; ++nt) {
            int col = wn * 64 + nt * 8 + 2 * (lane & 3);
            float2 wv  = *reinterpret_cast<const float2*>(&sW256[col]);
            float2 bbv = *reinterpret_cast<const float2*>(&b1[col]);
            float2 wwv = *reinterpret_cast<const float2*>(&W2[col]);
            float h0 = fmaf(yv0, wv.x, acc[mt][nt][0]) + bbv.x;
            float h1 = fmaf(yv0, wv.y, acc[mt][nt][1]) + bbv.y;
            float h2 = fmaf(yv1, wv.x, acc[mt][nt][2]) + bbv.x;
            float h3 = fmaf(yv1, wv.y, acc[mt][nt][3]) + bbv.y;
            s0[mt] += gelu_f(h0) * wwv.x;
            s0[mt] += gelu_f(h1) * wwv.y;
            s1[mt] += gelu_f(h2) * wwv.x;
            s1[mt] += gelu_f(h3) * wwv.y;
        }
    }
    #pragma unroll
    for (int mt = 0; mt < 2; ++mt) {
        s0[mt] += __shfl_xor_sync(0xffffffffu, s0[mt], 1);
        s0[mt] += __shfl_xor_sync(0xffffffffu, s0[mt], 2);
        s1[mt] += __shfl_xor_sync(0xffffffffu, s1[mt], 1);
        s1[mt] += __shfl_xor_sync(0xffffffffu, s1[mt], 2);
    }

    if ((lane & 3) == 0) {
        #pragma unroll
        for (int mt = 0; mt < 2; ++mt) {
            spart[wn * 64 + r0 + mt * 16]     = s0[mt];
            spart[wn * 64 + r0 + mt * 16 + 8] = s1[mt];
        }
    }
    __syncthreads();

    if (tid < 64) {
        float lg = spart[tid] + spart[64 + tid] + spart[128 + tid] + spart[192 + tid] + b2[0];
        if (sval[tid] < 0.5f) lg = -10000.0f;
        slog[tid] = lg;
    }
    __syncthreads();

    if (wid == 0) {                               // softmax over 64 y for this token
        float l0 = slog[lane], l1 = slog[32 + lane];
        float v0 = sval[lane], v1 = sval[32 + lane];
        float mx = fmaxf(l0, l1);
        #pragma unroll
        for (int s = 16; s > 0; s >>= 1) mx = fmaxf(mx, __shfl_xor_sync(0xffffffffu, mx, s));
        float e0 = expf(l0 - mx), e1 = expf(l1 - mx);
        float z = e0 + e1;
        #pragma unroll
        for (int s = 16; s > 0; s >>= 1) z += __shfl_xor_sync(0xffffffffu, z, s);
        float w0 = (e0 / z) * v0, w1 = (e1 / z) * v1;
        float s2 = w0 + w1;
        #pragma unroll
        for (int s = 16; s > 0; s >>= 1) s2 += __shfl_xor_sync(0xffffffffu, s2, s);
        float denom = fmaxf(s2, 1e-6f);
        swts[lane]      = w0 / denom;
        swts[32 + lane] = w1 / denom;
    }
    __syncthreads();

    // ---- out[bx][c] = sum_y w[y] * A_hi[y][c] from resident tile ----
    {
        const __half* Hi = reinterpret_cast<const __half*>(smem);
        float a = 0.f;
        #pragma unroll 8
        for (int y = 0; y < 64; ++y)
            a = fmaf(swts[y], __half2float(Hi[(uint32_t)y * SA_E + (uint32_t)tid]), a);
        out[(size_t)bx * 256 + tid] = a;
    }
}

extern "C" void kernel_launch(void* const* d_in, const int* in_sizes, int n_in,
                              void* d_out, int out_size) {
    (void)in_sizes; (void)n_in; (void)out_size;
    const float* sampled = (const float*)d_in[0];
    const float* valid   = (const float*)d_in[1];
    const float* y_norm  = (const float*)d_in[2];
    const float* W1      = (const float*)d_in[3];
    const float* b1      = (const float*)d_in[4];
    const float* W2      = (const float*)d_in[5];
    const float* b2      = (const float*)d_in[6];

    prep_B<<<256, 256>>>(W1);

    cudaFuncSetAttribute(dat_hmma_kernel, cudaFuncAttributeMaxDynamicSharedMemorySize, SMEM_TOTAL);
    dat_hmma_kernel<<<4096, 256, SMEM_TOTAL>>>(sampled, valid, y_norm, W1, b1, W2, b2, (float*)d_out);
}